// round 14
// baseline (speedup 1.0000x reference)
#include <cuda_runtime.h>
#include <cuda_fp16.h>
#include <cstdint>
#include <cstddef>

#define BATCH   16384
#define IN_F    768
#define OUT_F   768
#define KTOT    (9 * IN_F)         // 6912
#define BK      64
#define NKSTEPS (KTOT / BK)        // 108
#define BM      128
#define BN      128
#define NSTAGE  3
#define GEMM_THREADS 256
#define STAGE_BYTES  32768         // A 16KB + B 16KB
#define SMEM_BYTES   (NSTAGE * STAGE_BYTES + 1024)
#define NMTILES (BATCH / BM)       // 128

// Scratch (allocation-free rules): PHI [BATCH][KTOT] fp16 (226 MB), W [OUT_F][KTOT] fp16.
__device__ __align__(1024) __half g_phi[(size_t)BATCH * KTOT];
__device__ __align__(1024) __half g_w[(size_t)OUT_F * KTOT];
__device__ int g_flag[NMTILES];    // per-m-strip "PHI ready" flags

// ---------------- helpers ----------------
__device__ __forceinline__ uint32_t smem_u32(const void* p) {
    uint32_t a;
    asm("{ .reg .u64 t; cvta.to.shared.u64 t, %1; cvt.u32.u64 %0, t; }"
        : "=r"(a) : "l"(p));
    return a;
}
__device__ __forceinline__ void cp_async16(uint32_t dst, const void* src) {
    asm volatile("cp.async.cg.shared.global [%0], [%1], 16;" :: "r"(dst), "l"(src) : "memory");
}
__device__ __forceinline__ void cp_commit() {
    asm volatile("cp.async.commit_group;" ::: "memory");
}
template <int N>
__device__ __forceinline__ void cp_wait() {
    asm volatile("cp.async.wait_group %0;" :: "n"(N) : "memory");
}
__device__ __forceinline__ void ldsm_x4(uint32_t (&r)[4], uint32_t addr) {
    asm volatile("ldmatrix.sync.aligned.m8n8.x4.shared.b16 {%0,%1,%2,%3}, [%4];"
                 : "=r"(r[0]), "=r"(r[1]), "=r"(r[2]), "=r"(r[3]) : "r"(addr));
}
__device__ __forceinline__ void mma16816(float (&c)[4], const uint32_t (&a)[4],
                                         uint32_t b0, uint32_t b1) {
    asm volatile(
        "mma.sync.aligned.m16n8k16.row.col.f32.f16.f16.f32 "
        "{%0,%1,%2,%3}, {%4,%5,%6,%7}, {%8,%9}, {%0,%1,%2,%3};"
        : "+f"(c[0]), "+f"(c[1]), "+f"(c[2]), "+f"(c[3])
        : "r"(a[0]), "r"(a[1]), "r"(a[2]), "r"(a[3]), "r"(b0), "r"(b1));
}
__device__ __forceinline__ uint32_t swz(uint32_t off) {   // 128B-row xor swizzle
    return off ^ ((off >> 3) & 0x70);
}

// ---------------- pack W + zero flags (one small launch) ----------------
__global__ void __launch_bounds__(192, 8)
kan_pack(const float* __restrict__ wb, const float* __restrict__ ws,
         const float* __restrict__ c) {
    const int blk = blockIdx.x;
    if (blk == 0 && threadIdx.x < NMTILES) g_flag[threadIdx.x] = 0;
    const int aa = blk / OUT_F;           // uniform per block
    const int o  = blk - aa * OUT_F;
    const int i  = threadIdx.x * 4;
    float4 v;
    if (aa < 8) {
        float4 cv = *reinterpret_cast<const float4*>(c + ((size_t)aa * OUT_F + o) * IN_F + i);
        float4 wv = *reinterpret_cast<const float4*>(ws + (size_t)o * IN_F + i);
        v.x = cv.x * wv.x; v.y = cv.y * wv.y; v.z = cv.z * wv.z; v.w = cv.w * wv.w;
    } else {
        float4 bv = *reinterpret_cast<const float4*>(wb + (size_t)o * IN_F + i);
        v.x = bv.x * 64.0f; v.y = bv.y * 64.0f; v.z = bv.z * 64.0f; v.w = bv.w * 64.0f;
    }
    __half2 p01 = __floats2half2_rn(v.x, v.y);
    __half2 p23 = __floats2half2_rn(v.z, v.w);
    uint2 pk = { *reinterpret_cast<uint32_t*>(&p01), *reinterpret_cast<uint32_t*>(&p23) };
    *reinterpret_cast<uint2*>(g_w + (size_t)o * KTOT + (size_t)aa * IN_F + i) = pk;
}

// ---------------- GEMM with fused producer-side featurization ----------------
// n==0 CTA of each m-strip featurizes PHI rows [m0, m0+128) then releases g_flag[mt];
// sibling CTAs acquire the flag. GEMM body = proven R4 optimum.
__global__ void __launch_bounds__(GEMM_THREADS, 2)
kan_gemm(const float* __restrict__ x, float* __restrict__ out) {
    extern __shared__ char smem_raw[];
    const uint32_t sbase = (smem_u32(smem_raw) + 1023u) & ~1023u;

    const int tid = threadIdx.x;
    const int wid = tid >> 5;
    const int lid = tid & 31;
    const int wm  = wid & 1;          // 2 m-warps (64 rows each)
    const int wn  = wid >> 1;         // 4 n-warps (32 cols each)
    const int mt  = blockIdx.y;
    const int m0  = mt * BM;
    const int n0  = blockIdx.x * BN;

    // ---- producer/consumer phase for PHI m-strip ----
    if (blockIdx.x == 0) {
        // featurize 128 rows x 768 cols: 24576 float4 groups over 256 threads
#pragma unroll 1
        for (int it = 0; it < 96; it++) {
            int idx = tid + it * GEMM_THREADS;          // [0, 24576)
            int row = idx / 192;                        // 192 groups per row
            int g   = idx - row * 192;
            int b   = m0 + row;
            int i0  = g * 4;
            const float4 xv = *reinterpret_cast<const float4*>(x + (size_t)b * IN_F + i0);
            __half* dst = g_phi + (size_t)b * KTOT + i0;
            float zg0 = (xv.x + 2.0f) * 1.75f, zg1 = (xv.y + 2.0f) * 1.75f;
            float zg2 = (xv.z + 2.0f) * 1.75f, zg3 = (xv.w + 2.0f) * 1.75f;
#pragma unroll
            for (int a = 0; a < 8; a++) {
                float t0 = zg0 - (float)a, t1 = zg1 - (float)a;
                float t2 = zg2 - (float)a, t3 = zg3 - (float)a;
                __half2 p01 = __floats2half2_rn(__expf(-t0 * t0), __expf(-t1 * t1));
                __half2 p23 = __floats2half2_rn(__expf(-t2 * t2), __expf(-t3 * t3));
                uint2 pk = { *reinterpret_cast<uint32_t*>(&p01),
                             *reinterpret_cast<uint32_t*>(&p23) };
                *reinterpret_cast<uint2*>(dst + (size_t)a * IN_F) = pk;
            }
            float s0 = xv.x / (1.0f + __expf(-xv.x)) * 0.015625f;   // silu/64 rebalance
            float s1 = xv.y / (1.0f + __expf(-xv.y)) * 0.015625f;
            float s2 = xv.z / (1.0f + __expf(-xv.z)) * 0.015625f;
            float s3 = xv.w / (1.0f + __expf(-xv.w)) * 0.015625f;
            __half2 q01 = __floats2half2_rn(s0, s1);
            __half2 q23 = __floats2half2_rn(s2, s3);
            uint2 qk = { *reinterpret_cast<uint32_t*>(&q01),
                         *reinterpret_cast<uint32_t*>(&q23) };
            *reinterpret_cast<uint2*>(dst + (size_t)8 * IN_F) = qk;
        }
        __threadfence();              // release PHI writes (and order before own cp.async)
        __syncthreads();
        if (tid == 0) atomicExch(&g_flag[mt], 1);
    } else {
        if (tid == 0) {
            while (atomicAdd(&g_flag[mt], 0) == 0) __nanosleep(128);
            __threadfence();          // acquire
        }
        __syncthreads();
    }

    // ---- GEMM body (R4 optimum) ----
    const __half* aCol = g_phi + (size_t)m0 * KTOT;
    const __half* bCol = g_w   + (size_t)n0 * KTOT;

    auto load_stage = [&](int kstep, int s) {
        const uint32_t sA = sbase + (uint32_t)s * STAGE_BYTES;
        const uint32_t sB = sA + 16384;
        const __half* aSrc = aCol + kstep * BK;
        const __half* bSrc = bCol + kstep * BK;
#pragma unroll
        for (int j = 0; j < 4; j++) {
            int q = tid + j * GEMM_THREADS;
            cp_async16(sA + swz((uint32_t)q << 4),
                       aSrc + (size_t)(q >> 3) * KTOT + ((q & 7) << 3));
        }
#pragma unroll
        for (int j = 0; j < 4; j++) {
            int q = tid + j * GEMM_THREADS;
            cp_async16(sB + swz((uint32_t)q << 4),
                       bSrc + (size_t)(q >> 3) * KTOT + ((q & 7) << 3));
        }
    };

    load_stage(0, 0); cp_commit();
    load_stage(1, 1); cp_commit();

    float acc[4][4][4];
#pragma unroll
    for (int mi = 0; mi < 4; mi++)
#pragma unroll
        for (int ni = 0; ni < 4; ni++)
#pragma unroll
            for (int r = 0; r < 4; r++) acc[mi][ni][r] = 0.0f;

    const uint32_t aRowOff = (uint32_t)(wm * 64 + (lid & 15)) * 128;
    const uint32_t aColB   = (uint32_t)(lid >> 4) * 16;
    const uint32_t bRowOff = (uint32_t)(wn * 32 + (lid >> 4) * 8 + (lid & 7)) * 128;
    const uint32_t bColB   = (uint32_t)((lid >> 3) & 1) * 16;

    uint32_t afrag[2][4][4];   // [buf][mi][reg]
    uint32_t bfrag[2][2][4];   // [buf][nb][reg]

    auto load_frags = [&](int buf, uint32_t sA, uint32_t sB, int kk) {
#pragma unroll
        for (int mi = 0; mi < 4; mi++)
            ldsm_x4(afrag[buf][mi], sA + swz(aRowOff + (uint32_t)(mi * 16) * 128 +
                                             aColB + (uint32_t)kk * 32));
#pragma unroll
        for (int nb = 0; nb < 2; nb++)
            ldsm_x4(bfrag[buf][nb], sB + swz(bRowOff + (uint32_t)(nb * 16) * 128 +
                                             bColB + (uint32_t)kk * 32));
    };
    auto mma_step = [&](int buf) {
#pragma unroll
        for (int nb = 0; nb < 2; nb++)
#pragma unroll
            for (int mi = 0; mi < 4; mi++) {
                mma16816(acc[mi][2 * nb],     afrag[buf][mi],
                         bfrag[buf][nb][0], bfrag[buf][nb][1]);
                mma16816(acc[mi][2 * nb + 1], afrag[buf][mi],
                         bfrag[buf][nb][2], bfrag[buf][nb][3]);
            }
    };

    int stage = 0;
#pragma unroll 1
    for (int k = 0; k < NKSTEPS; k++) {
        cp_wait<1>();
        __syncthreads();

        if (k + 2 < NKSTEPS) {
            int s2 = stage + 2; if (s2 >= NSTAGE) s2 -= NSTAGE;
            load_stage(k + 2, s2);
        }
        cp_commit();

        const uint32_t sA = sbase + (uint32_t)stage * STAGE_BYTES;
        const uint32_t sB = sA + 16384;

        load_frags(0, sA, sB, 0);
#pragma unroll
        for (int kk = 0; kk < 4; kk++) {
            if (kk < 3) load_frags((kk + 1) & 1, sA, sB, kk + 1);
            mma_step(kk & 1);
        }
        if (++stage == NSTAGE) stage = 0;
    }

    // Epilogue: C frags -> global float2 stores
    const int gr = lid >> 2;
    const int tg = lid & 3;
    float* obase = out + (size_t)(m0 + wm * 64) * OUT_F + n0 + wn * 32;
#pragma unroll
    for (int mi = 0; mi < 4; mi++) {
#pragma unroll
        for (int ni = 0; ni < 4; ni++) {
            int row0 = mi * 16 + gr;
            int col  = ni * 8 + 2 * tg;
            float2 v0 = { acc[mi][ni][0], acc[mi][ni][1] };
            float2 v1 = { acc[mi][ni][2], acc[mi][ni][3] };
            *reinterpret_cast<float2*>(obase + (size_t)row0 * OUT_F + col)       = v0;
            *reinterpret_cast<float2*>(obase + (size_t)(row0 + 8) * OUT_F + col) = v1;
        }
    }
}

extern "C" void kernel_launch(void* const* d_in, const int* in_sizes, int n_in,
                              void* d_out, int out_size) {
    const float* x  = (const float*)d_in[0];
    const float* wb = (const float*)d_in[1];
    const float* ws = (const float*)d_in[2];
    const float* c  = (const float*)d_in[3];
    float* out = (float*)d_out;

    cudaFuncSetAttribute(kan_gemm, cudaFuncAttributeMaxDynamicSharedMemorySize, SMEM_BYTES);

    kan_pack<<<9 * OUT_F, 192>>>(wb, ws, c);
    kan_gemm<<<dim3(OUT_F / BN, NMTILES), GEMM_THREADS, SMEM_BYTES>>>(x, out);
}

// round 15
// speedup vs baseline: 1.4657x; 1.4657x over previous
#include <cuda_runtime.h>
#include <cuda_fp16.h>
#include <cstdint>
#include <cstddef>

#define BATCH   16384
#define IN_F    768
#define OUT_F   768
#define KTOT    (9 * IN_F)         // 6912
#define BK      64
#define NKSTEPS (KTOT / BK)        // 108
#define BM      128
#define BN      128
#define NSTAGE  3
#define GEMM_THREADS 256
#define STAGE_BYTES  32768         // A 16KB + B 16KB
#define SMEM_BYTES   (NSTAGE * STAGE_BYTES + 1024)

#define PACK_BLKS (9 * OUT_F)      // 6912 blocks for pack
#define FEAT_BLKS BATCH            // 16384 blocks for feat

// Scratch (allocation-free rules): PHI [BATCH][KTOT] fp16 (226 MB), W [OUT_F][KTOT] fp16.
__device__ __align__(1024) __half g_phi[(size_t)BATCH * KTOT];
__device__ __align__(1024) __half g_w[(size_t)OUT_F * KTOT];

// ---------------- helpers ----------------
__device__ __forceinline__ uint32_t smem_u32(const void* p) {
    uint32_t a;
    asm("{ .reg .u64 t; cvta.to.shared.u64 t, %1; cvt.u32.u64 %0, t; }"
        : "=r"(a) : "l"(p));
    return a;
}
__device__ __forceinline__ void cp_async16(uint32_t dst, const void* src) {
    asm volatile("cp.async.cg.shared.global [%0], [%1], 16;" :: "r"(dst), "l"(src) : "memory");
}
__device__ __forceinline__ void cp_commit() {
    asm volatile("cp.async.commit_group;" ::: "memory");
}
template <int N>
__device__ __forceinline__ void cp_wait() {
    asm volatile("cp.async.wait_group %0;" :: "n"(N) : "memory");
}
__device__ __forceinline__ void ldsm_x4(uint32_t (&r)[4], uint32_t addr) {
    asm volatile("ldmatrix.sync.aligned.m8n8.x4.shared.b16 {%0,%1,%2,%3}, [%4];"
                 : "=r"(r[0]), "=r"(r[1]), "=r"(r[2]), "=r"(r[3]) : "r"(addr));
}
__device__ __forceinline__ void mma16816(float (&c)[4], const uint32_t (&a)[4],
                                         uint32_t b0, uint32_t b1) {
    asm volatile(
        "mma.sync.aligned.m16n8k16.row.col.f32.f16.f16.f32 "
        "{%0,%1,%2,%3}, {%4,%5,%6,%7}, {%8,%9}, {%0,%1,%2,%3};"
        : "+f"(c[0]), "+f"(c[1]), "+f"(c[2]), "+f"(c[3])
        : "r"(a[0]), "r"(a[1]), "r"(a[2]), "r"(a[3]), "r"(b0), "r"(b1));
}
__device__ __forceinline__ uint32_t swz(uint32_t off) {   // 128B-row xor swizzle
    return off ^ ((off >> 3) & 0x70);
}
__device__ __forceinline__ void stg_cs_f2(float* p, float2 v) {   // streaming store
    asm volatile("st.global.cs.v2.f32 [%0], {%1, %2};" :: "l"(p), "f"(v.x), "f"(v.y)
                 : "memory");
}

// ---------------- fused prep: blocks [0,PACK_BLKS) pack W; rest featurize PHI ----------------
__global__ void __launch_bounds__(192, 8)
kan_prep(const float* __restrict__ x,  const float* __restrict__ wb,
         const float* __restrict__ ws, const float* __restrict__ c) {
    const int blk = blockIdx.x;
    if (blk < PACK_BLKS) {
        // pack: one block per (a, o), 4 elems/thread, div is uniform per block
        const int aa = blk / OUT_F;
        const int o  = blk - aa * OUT_F;
        const int i  = threadIdx.x * 4;
        float4 v;
        if (aa < 8) {
            float4 cv = *reinterpret_cast<const float4*>(c + ((size_t)aa * OUT_F + o) * IN_F + i);
            float4 wv = *reinterpret_cast<const float4*>(ws + (size_t)o * IN_F + i);
            v.x = cv.x * wv.x; v.y = cv.y * wv.y; v.z = cv.z * wv.z; v.w = cv.w * wv.w;
        } else {
            float4 bv = *reinterpret_cast<const float4*>(wb + (size_t)o * IN_F + i);
            v.x = bv.x * 64.0f; v.y = bv.y * 64.0f; v.z = bv.z * 64.0f; v.w = bv.w * 64.0f;
        }
        __half2 p01 = __floats2half2_rn(v.x, v.y);
        __half2 p23 = __floats2half2_rn(v.z, v.w);
        uint2 pk = { *reinterpret_cast<uint32_t*>(&p01), *reinterpret_cast<uint32_t*>(&p23) };
        *reinterpret_cast<uint2*>(g_w + (size_t)o * KTOT + (size_t)aa * IN_F + i) = pk;
    } else {
        // featurize: one block per batch row, 4 elems/thread
        const int b  = blk - PACK_BLKS;
        const int i0 = threadIdx.x * 4;
        const float4 xv = *reinterpret_cast<const float4*>(x + (size_t)b * IN_F + i0);
        __half* dst = g_phi + (size_t)b * KTOT + i0;
        float zg[4] = { (xv.x + 2.0f) * 1.75f, (xv.y + 2.0f) * 1.75f,
                        (xv.z + 2.0f) * 1.75f, (xv.w + 2.0f) * 1.75f };
#pragma unroll
        for (int a = 0; a < 8; a++) {
            float t0 = zg[0] - (float)a, t1 = zg[1] - (float)a;
            float t2 = zg[2] - (float)a, t3 = zg[3] - (float)a;
            __half2 p01 = __floats2half2_rn(__expf(-t0 * t0), __expf(-t1 * t1));
            __half2 p23 = __floats2half2_rn(__expf(-t2 * t2), __expf(-t3 * t3));
            uint2 pk = { *reinterpret_cast<uint32_t*>(&p01), *reinterpret_cast<uint32_t*>(&p23) };
            *reinterpret_cast<uint2*>(dst + (size_t)a * IN_F) = pk;
        }
        float s0 = xv.x / (1.0f + __expf(-xv.x)) * 0.015625f;   // silu/64 rebalance
        float s1 = xv.y / (1.0f + __expf(-xv.y)) * 0.015625f;
        float s2 = xv.z / (1.0f + __expf(-xv.z)) * 0.015625f;
        float s3 = xv.w / (1.0f + __expf(-xv.w)) * 0.015625f;
        __half2 q01 = __floats2half2_rn(s0, s1);
        __half2 q23 = __floats2half2_rn(s2, s3);
        uint2 qk = { *reinterpret_cast<uint32_t*>(&q01), *reinterpret_cast<uint32_t*>(&q23) };
        *reinterpret_cast<uint2*>(dst + (size_t)8 * IN_F) = qk;
    }
}

// ---------------- GEMM: out = PHI x W^T (proven R4/R12 optimum) ----------------
// BM=128 x BN=128, BK=64, 8 warps (2m x 4n), warp tile 64x32.
// 3-stage cp.async ring, 1 barrier/k-iter, 2 CTAs/SM, reg double-buffered frags.
// Epilogue uses streaming (evict-first) stores: output is write-once, keep L2 for A/B.
__global__ void __launch_bounds__(GEMM_THREADS, 2)
kan_gemm(float* __restrict__ out) {
    extern __shared__ char smem_raw[];
    const uint32_t sbase = (smem_u32(smem_raw) + 1023u) & ~1023u;

    const int tid = threadIdx.x;
    const int wid = tid >> 5;
    const int lid = tid & 31;
    const int wm  = wid & 1;          // 2 m-warps (64 rows each)
    const int wn  = wid >> 1;         // 4 n-warps (32 cols each)
    const int m0  = blockIdx.y * BM;
    const int n0  = blockIdx.x * BN;

    const __half* aCol = g_phi + (size_t)m0 * KTOT;
    const __half* bCol = g_w   + (size_t)n0 * KTOT;

    auto load_stage = [&](int kstep, int s) {
        const uint32_t sA = sbase + (uint32_t)s * STAGE_BYTES;
        const uint32_t sB = sA + 16384;
        const __half* aSrc = aCol + kstep * BK;
        const __half* bSrc = bCol + kstep * BK;
#pragma unroll
        for (int j = 0; j < 4; j++) {
            int q = tid + j * GEMM_THREADS;
            cp_async16(sA + swz((uint32_t)q << 4),
                       aSrc + (size_t)(q >> 3) * KTOT + ((q & 7) << 3));
        }
#pragma unroll
        for (int j = 0; j < 4; j++) {
            int q = tid + j * GEMM_THREADS;
            cp_async16(sB + swz((uint32_t)q << 4),
                       bSrc + (size_t)(q >> 3) * KTOT + ((q & 7) << 3));
        }
    };

    load_stage(0, 0); cp_commit();
    load_stage(1, 1); cp_commit();

    float acc[4][4][4];
#pragma unroll
    for (int mi = 0; mi < 4; mi++)
#pragma unroll
        for (int ni = 0; ni < 4; ni++)
#pragma unroll
            for (int r = 0; r < 4; r++) acc[mi][ni][r] = 0.0f;

    // ldmatrix lane addressing (byte offsets within tile, swizzled per 128B row)
    const uint32_t aRowOff = (uint32_t)(wm * 64 + (lid & 15)) * 128;            // + mi*16*128
    const uint32_t aColB   = (uint32_t)(lid >> 4) * 16;                          // + kk*32
    const uint32_t bRowOff = (uint32_t)(wn * 32 + (lid >> 4) * 8 + (lid & 7)) * 128; // + nb*16*128
    const uint32_t bColB   = (uint32_t)((lid >> 3) & 1) * 16;                    // + kk*32

    uint32_t afrag[2][4][4];   // [buf][mi][reg]
    uint32_t bfrag[2][2][4];   // [buf][nb][reg]

    auto load_frags = [&](int buf, uint32_t sA, uint32_t sB, int kk) {
#pragma unroll
        for (int mi = 0; mi < 4; mi++)
            ldsm_x4(afrag[buf][mi], sA + swz(aRowOff + (uint32_t)(mi * 16) * 128 +
                                             aColB + (uint32_t)kk * 32));
#pragma unroll
        for (int nb = 0; nb < 2; nb++)
            ldsm_x4(bfrag[buf][nb], sB + swz(bRowOff + (uint32_t)(nb * 16) * 128 +
                                             bColB + (uint32_t)kk * 32));
    };
    auto mma_step = [&](int buf) {
#pragma unroll
        for (int nb = 0; nb < 2; nb++)
#pragma unroll
            for (int mi = 0; mi < 4; mi++) {
                mma16816(acc[mi][2 * nb],     afrag[buf][mi],
                         bfrag[buf][nb][0], bfrag[buf][nb][1]);
                mma16816(acc[mi][2 * nb + 1], afrag[buf][mi],
                         bfrag[buf][nb][2], bfrag[buf][nb][3]);
            }
    };

    int stage = 0;
#pragma unroll 1
    for (int k = 0; k < NKSTEPS; k++) {
        cp_wait<1>();
        __syncthreads();

        // prefetch stage k+2 into the buffer freed last iter (safe: barrier above)
        if (k + 2 < NKSTEPS) {
            int s2 = stage + 2; if (s2 >= NSTAGE) s2 -= NSTAGE;
            load_stage(k + 2, s2);
        }
        cp_commit();   // unconditional: uniform wait_group counting at the tail

        const uint32_t sA = sbase + (uint32_t)stage * STAGE_BYTES;
        const uint32_t sB = sA + 16384;

        load_frags(0, sA, sB, 0);
#pragma unroll
        for (int kk = 0; kk < 4; kk++) {
            if (kk < 3) load_frags((kk + 1) & 1, sA, sB, kk + 1);
            mma_step(kk & 1);
        }
        if (++stage == NSTAGE) stage = 0;
    }

    // Epilogue: C frags -> global, streaming float2 stores (write-once output)
    const int gr = lid >> 2;
    const int tg = lid & 3;
    float* obase = out + (size_t)(m0 + wm * 64) * OUT_F + n0 + wn * 32;
#pragma unroll
    for (int mi = 0; mi < 4; mi++) {
#pragma unroll
        for (int ni = 0; ni < 4; ni++) {
            int row0 = mi * 16 + gr;
            int col  = ni * 8 + 2 * tg;
            float2 v0 = { acc[mi][ni][0], acc[mi][ni][1] };
            float2 v1 = { acc[mi][ni][2], acc[mi][ni][3] };
            stg_cs_f2(obase + (size_t)row0 * OUT_F + col,       v0);
            stg_cs_f2(obase + (size_t)(row0 + 8) * OUT_F + col, v1);
        }
    }
}

extern "C" void kernel_launch(void* const* d_in, const int* in_sizes, int n_in,
                              void* d_out, int out_size) {
    const float* x  = (const float*)d_in[0];
    const float* wb = (const float*)d_in[1];
    const float* ws = (const float*)d_in[2];
    const float* c  = (const float*)d_in[3];
    float* out = (float*)d_out;

    cudaFuncSetAttribute(kan_gemm, cudaFuncAttributeMaxDynamicSharedMemorySize, SMEM_BYTES);

    kan_prep<<<PACK_BLKS + FEAT_BLKS, 192>>>(x, wb, ws, c);
    kan_gemm<<<dim3(OUT_F / BN, BATCH / BM), GEMM_THREADS, SMEM_BYTES>>>(out);
}

// round 16
// speedup vs baseline: 1.4697x; 1.0027x over previous
#include <cuda_runtime.h>
#include <cuda_fp16.h>
#include <cstdint>
#include <cstddef>

#define BATCH   16384
#define IN_F    768
#define OUT_F   768
#define KTOT    (9 * IN_F)         // 6912
#define BK      64
#define NKSTEPS (KTOT / BK)        // 108
#define BM      128
#define BN      128
#define NSTAGE  3
#define GEMM_THREADS 256
#define STAGE_BYTES  32768         // A 16KB + B 16KB
#define SMEM_BYTES   (NSTAGE * STAGE_BYTES + 1024)

#define PACK_BLKS (9 * OUT_F)      // 6912 blocks for pack
#define FEAT_BLKS BATCH            // 16384 blocks for feat

// Scratch (allocation-free rules): PHI [BATCH][KTOT] fp16 (226 MB), W [OUT_F][KTOT] fp16.
__device__ __align__(1024) __half g_phi[(size_t)BATCH * KTOT];
__device__ __align__(1024) __half g_w[(size_t)OUT_F * KTOT];

// ---------------- helpers ----------------
__device__ __forceinline__ uint32_t smem_u32(const void* p) {
    uint32_t a;
    asm("{ .reg .u64 t; cvta.to.shared.u64 t, %1; cvt.u32.u64 %0, t; }"
        : "=r"(a) : "l"(p));
    return a;
}
__device__ __forceinline__ void cp_async16(uint32_t dst, const void* src) {
    asm volatile("cp.async.cg.shared.global [%0], [%1], 16;" :: "r"(dst), "l"(src) : "memory");
}
__device__ __forceinline__ void cp_commit() {
    asm volatile("cp.async.commit_group;" ::: "memory");
}
template <int N>
__device__ __forceinline__ void cp_wait() {
    asm volatile("cp.async.wait_group %0;" :: "n"(N) : "memory");
}
__device__ __forceinline__ void ldsm_x4(uint32_t (&r)[4], uint32_t addr) {
    asm volatile("ldmatrix.sync.aligned.m8n8.x4.shared.b16 {%0,%1,%2,%3}, [%4];"
                 : "=r"(r[0]), "=r"(r[1]), "=r"(r[2]), "=r"(r[3]) : "r"(addr));
}
__device__ __forceinline__ void mma16816(float (&c)[4], const uint32_t (&a)[4],
                                         uint32_t b0, uint32_t b1) {
    asm volatile(
        "mma.sync.aligned.m16n8k16.row.col.f32.f16.f16.f32 "
        "{%0,%1,%2,%3}, {%4,%5,%6,%7}, {%8,%9}, {%0,%1,%2,%3};"
        : "+f"(c[0]), "+f"(c[1]), "+f"(c[2]), "+f"(c[3])
        : "r"(a[0]), "r"(a[1]), "r"(a[2]), "r"(a[3]), "r"(b0), "r"(b1));
}
__device__ __forceinline__ uint32_t swz(uint32_t off) {   // 128B-row xor swizzle
    return off ^ ((off >> 3) & 0x70);
}

// ---------------- fused prep: blocks [0,PACK_BLKS) pack W; rest featurize PHI ----------------
__global__ void __launch_bounds__(192, 8)
kan_prep(const float* __restrict__ x,  const float* __restrict__ wb,
         const float* __restrict__ ws, const float* __restrict__ c) {
    const int blk = blockIdx.x;
    if (blk < PACK_BLKS) {
        // pack: one block per (a, o), 4 elems/thread, div is uniform per block
        const int aa = blk / OUT_F;
        const int o  = blk - aa * OUT_F;
        const int i  = threadIdx.x * 4;
        float4 v;
        if (aa < 8) {
            float4 cv = *reinterpret_cast<const float4*>(c + ((size_t)aa * OUT_F + o) * IN_F + i);
            float4 wv = *reinterpret_cast<const float4*>(ws + (size_t)o * IN_F + i);
            v.x = cv.x * wv.x; v.y = cv.y * wv.y; v.z = cv.z * wv.z; v.w = cv.w * wv.w;
        } else {
            float4 bv = *reinterpret_cast<const float4*>(wb + (size_t)o * IN_F + i);
            v.x = bv.x * 64.0f; v.y = bv.y * 64.0f; v.z = bv.z * 64.0f; v.w = bv.w * 64.0f;
        }
        __half2 p01 = __floats2half2_rn(v.x, v.y);
        __half2 p23 = __floats2half2_rn(v.z, v.w);
        uint2 pk = { *reinterpret_cast<uint32_t*>(&p01), *reinterpret_cast<uint32_t*>(&p23) };
        *reinterpret_cast<uint2*>(g_w + (size_t)o * KTOT + (size_t)aa * IN_F + i) = pk;
    } else {
        // featurize: one block per batch row, 4 elems/thread
        const int b  = blk - PACK_BLKS;
        const int i0 = threadIdx.x * 4;
        const float4 xv = *reinterpret_cast<const float4*>(x + (size_t)b * IN_F + i0);
        __half* dst = g_phi + (size_t)b * KTOT + i0;
        float zg[4] = { (xv.x + 2.0f) * 1.75f, (xv.y + 2.0f) * 1.75f,
                        (xv.z + 2.0f) * 1.75f, (xv.w + 2.0f) * 1.75f };
#pragma unroll
        for (int a = 0; a < 8; a++) {
            float t0 = zg[0] - (float)a, t1 = zg[1] - (float)a;
            float t2 = zg[2] - (float)a, t3 = zg[3] - (float)a;
            __half2 p01 = __floats2half2_rn(__expf(-t0 * t0), __expf(-t1 * t1));
            __half2 p23 = __floats2half2_rn(__expf(-t2 * t2), __expf(-t3 * t3));
            uint2 pk = { *reinterpret_cast<uint32_t*>(&p01), *reinterpret_cast<uint32_t*>(&p23) };
            *reinterpret_cast<uint2*>(dst + (size_t)a * IN_F) = pk;
        }
        float s0 = xv.x / (1.0f + __expf(-xv.x)) * 0.015625f;   // silu/64 rebalance
        float s1 = xv.y / (1.0f + __expf(-xv.y)) * 0.015625f;
        float s2 = xv.z / (1.0f + __expf(-xv.z)) * 0.015625f;
        float s3 = xv.w / (1.0f + __expf(-xv.w)) * 0.015625f;
        __half2 q01 = __floats2half2_rn(s0, s1);
        __half2 q23 = __floats2half2_rn(s2, s3);
        uint2 qk = { *reinterpret_cast<uint32_t*>(&q01), *reinterpret_cast<uint32_t*>(&q23) };
        *reinterpret_cast<uint2*>(dst + (size_t)8 * IN_F) = qk;
    }
}

// ---------------- GEMM: out = PHI x W^T (verified optimum config) ----------------
// BM=128 x BN=128, BK=64, 8 warps (2m x 4n), warp tile 64x32.
// 3-stage cp.async ring, 1 barrier/k-iter, 2 CTAs/SM, reg double-buffered frags.
__global__ void __launch_bounds__(GEMM_THREADS, 2)
kan_gemm(float* __restrict__ out) {
    extern __shared__ char smem_raw[];
    const uint32_t sbase = (smem_u32(smem_raw) + 1023u) & ~1023u;

    const int tid = threadIdx.x;
    const int wid = tid >> 5;
    const int lid = tid & 31;
    const int wm  = wid & 1;          // 2 m-warps (64 rows each)
    const int wn  = wid >> 1;         // 4 n-warps (32 cols each)
    const int m0  = blockIdx.y * BM;
    const int n0  = blockIdx.x * BN;

    const __half* aCol = g_phi + (size_t)m0 * KTOT;
    const __half* bCol = g_w   + (size_t)n0 * KTOT;

    auto load_stage = [&](int kstep, int s) {
        const uint32_t sA = sbase + (uint32_t)s * STAGE_BYTES;
        const uint32_t sB = sA + 16384;
        const __half* aSrc = aCol + kstep * BK;
        const __half* bSrc = bCol + kstep * BK;
#pragma unroll
        for (int j = 0; j < 4; j++) {
            int q = tid + j * GEMM_THREADS;
            cp_async16(sA + swz((uint32_t)q << 4),
                       aSrc + (size_t)(q >> 3) * KTOT + ((q & 7) << 3));
        }
#pragma unroll
        for (int j = 0; j < 4; j++) {
            int q = tid + j * GEMM_THREADS;
            cp_async16(sB + swz((uint32_t)q << 4),
                       bSrc + (size_t)(q >> 3) * KTOT + ((q & 7) << 3));
        }
    };

    load_stage(0, 0); cp_commit();
    load_stage(1, 1); cp_commit();

    float acc[4][4][4];
#pragma unroll
    for (int mi = 0; mi < 4; mi++)
#pragma unroll
        for (int ni = 0; ni < 4; ni++)
#pragma unroll
            for (int r = 0; r < 4; r++) acc[mi][ni][r] = 0.0f;

    // ldmatrix lane addressing (byte offsets within tile, swizzled per 128B row)
    const uint32_t aRowOff = (uint32_t)(wm * 64 + (lid & 15)) * 128;            // + mi*16*128
    const uint32_t aColB   = (uint32_t)(lid >> 4) * 16;                          // + kk*32
    const uint32_t bRowOff = (uint32_t)(wn * 32 + (lid >> 4) * 8 + (lid & 7)) * 128; // + nb*16*128
    const uint32_t bColB   = (uint32_t)((lid >> 3) & 1) * 16;                    // + kk*32

    uint32_t afrag[2][4][4];   // [buf][mi][reg]
    uint32_t bfrag[2][2][4];   // [buf][nb][reg]

    auto load_frags = [&](int buf, uint32_t sA, uint32_t sB, int kk) {
#pragma unroll
        for (int mi = 0; mi < 4; mi++)
            ldsm_x4(afrag[buf][mi], sA + swz(aRowOff + (uint32_t)(mi * 16) * 128 +
                                             aColB + (uint32_t)kk * 32));
#pragma unroll
        for (int nb = 0; nb < 2; nb++)
            ldsm_x4(bfrag[buf][nb], sB + swz(bRowOff + (uint32_t)(nb * 16) * 128 +
                                             bColB + (uint32_t)kk * 32));
    };
    auto mma_step = [&](int buf) {
#pragma unroll
        for (int nb = 0; nb < 2; nb++)
#pragma unroll
            for (int mi = 0; mi < 4; mi++) {
                mma16816(acc[mi][2 * nb],     afrag[buf][mi],
                         bfrag[buf][nb][0], bfrag[buf][nb][1]);
                mma16816(acc[mi][2 * nb + 1], afrag[buf][mi],
                         bfrag[buf][nb][2], bfrag[buf][nb][3]);
            }
    };

    int stage = 0;
#pragma unroll 1
    for (int k = 0; k < NKSTEPS; k++) {
        cp_wait<1>();
        __syncthreads();

        // prefetch stage k+2 into the buffer freed last iter (safe: barrier above)
        if (k + 2 < NKSTEPS) {
            int s2 = stage + 2; if (s2 >= NSTAGE) s2 -= NSTAGE;
            load_stage(k + 2, s2);
        }
        cp_commit();   // unconditional: uniform wait_group counting at the tail

        const uint32_t sA = sbase + (uint32_t)stage * STAGE_BYTES;
        const uint32_t sB = sA + 16384;

        load_frags(0, sA, sB, 0);
#pragma unroll
        for (int kk = 0; kk < 4; kk++) {
            if (kk < 3) load_frags((kk + 1) & 1, sA, sB, kk + 1);
            mma_step(kk & 1);
        }
        if (++stage == NSTAGE) stage = 0;
    }

    // Epilogue: C frags -> global float2 stores
    const int gr = lid >> 2;
    const int tg = lid & 3;
    float* obase = out + (size_t)(m0 + wm * 64) * OUT_F + n0 + wn * 32;
#pragma unroll
    for (int mi = 0; mi < 4; mi++) {
#pragma unroll
        for (int ni = 0; ni < 4; ni++) {
            int row0 = mi * 16 + gr;
            int col  = ni * 8 + 2 * tg;
            float2 v0 = { acc[mi][ni][0], acc[mi][ni][1] };
            float2 v1 = { acc[mi][ni][2], acc[mi][ni][3] };
            *reinterpret_cast<float2*>(obase + (size_t)row0 * OUT_F + col)       = v0;
            *reinterpret_cast<float2*>(obase + (size_t)(row0 + 8) * OUT_F + col) = v1;
        }
    }
}

extern "C" void kernel_launch(void* const* d_in, const int* in_sizes, int n_in,
                              void* d_out, int out_size) {
    const float* x  = (const float*)d_in[0];
    const float* wb = (const float*)d_in[1];
    const float* ws = (const float*)d_in[2];
    const float* c  = (const float*)d_in[3];
    float* out = (float*)d_out;

    cudaFuncSetAttribute(kan_gemm, cudaFuncAttributeMaxDynamicSharedMemorySize, SMEM_BYTES);

    kan_prep<<<PACK_BLKS + FEAT_BLKS, 192>>>(x, wb, ws, c);
    kan_gemm<<<dim3(OUT_F / BN, BATCH / BM), GEMM_THREADS, SMEM_BYTES>>>(out);
}